// round 6
// baseline (speedup 1.0000x reference)
#include <cuda_runtime.h>
#include <cstdint>
#include <math.h>

// Problem constants
#define Hd   100
#define Fdim 40
#define Nn   32
#define Bb   256
#define EFd  4
#define OUTD 128
#define PASSES 3
#define TPB  256
#define MAXNBR 16
#define RS   33      // padded row stride (odd -> conflict-free strided smem access)
#define EROW 132     // edge-stage row stride in floats

// ---- Pre-transposed weights (rebuilt by prep_kernel every launch; deterministic) ----
// Type-interleaved msg weights: g_W2i[((h*25 + g)*4) + t] = float4 { W_msg[m=4g..4g+3, h, f=t] }
// -> for fixed (h,g) the 4 types span 64B: lane-divergent type loads hit ONE 128B line.
__device__ __align__(128) float4 g_W2i[Hd * 25 * EFd];
// g_WP[(hh2*100 + g)*3 + k] : 12 packed GRU weights for gate-row g, reduction rows hh=2*hh2, 2*hh2+1
//   k0 = {ih_r0, ih_z0, ih_n0, hh_r0}
//   k1 = {hh_z0, hh_n0, ir1, iz1}
//   k2 = {in1, hh_r1, hh_z1, hh_n1}
__device__ __align__(16) float4 g_WP[(Hd / 2) * Hd * 3];
// g_BI[g] = {b_ih_r+b_hh_r, b_ih_z+b_hh_z, b_ih_n, b_hh_n}
__device__ __align__(16) float4 g_BI[Hd];

__global__ void prep_kernel(const float* __restrict__ W_msg,
                            const float* __restrict__ W_ih,
                            const float* __restrict__ W_hh,
                            const float* __restrict__ b_ih,
                            const float* __restrict__ b_hh) {
    int t0 = blockIdx.x * blockDim.x + threadIdx.x;
    int stride = gridDim.x * blockDim.x;
    // W_msg (M,H,EF) -> [(h*25+g)*4 + t] float4 over m=4g..4g+3
    for (int idx = t0; idx < Hd * 25 * EFd; idx += stride) {
        int t  = idx & 3;
        int hg = idx >> 2;
        int g  = hg % 25;
        int h  = hg / 25;
        float4 v;
        v.x = W_msg[((4 * g + 0) * Hd + h) * EFd + t];
        v.y = W_msg[((4 * g + 1) * Hd + h) * EFd + t];
        v.z = W_msg[((4 * g + 2) * Hd + h) * EFd + t];
        v.w = W_msg[((4 * g + 3) * Hd + h) * EFd + t];
        g_W2i[idx] = v;
    }
    // GRU packed weights
    for (int idx = t0; idx < (Hd / 2) * Hd; idx += stride) {
        int g   = idx % Hd;
        int hh2 = idx / Hd;
        int h0 = 2 * hh2, h1 = 2 * hh2 + 1;
        float ir0 = W_ih[(g          ) * Hd + h0];
        float iz0 = W_ih[(Hd + g     ) * Hd + h0];
        float in0 = W_ih[(2 * Hd + g ) * Hd + h0];
        float hr0 = W_hh[(g          ) * Hd + h0];
        float hz0 = W_hh[(Hd + g     ) * Hd + h0];
        float hn0 = W_hh[(2 * Hd + g ) * Hd + h0];
        float ir1 = W_ih[(g          ) * Hd + h1];
        float iz1 = W_ih[(Hd + g     ) * Hd + h1];
        float in1 = W_ih[(2 * Hd + g ) * Hd + h1];
        float hr1 = W_hh[(g          ) * Hd + h1];
        float hz1 = W_hh[(Hd + g     ) * Hd + h1];
        float hn1 = W_hh[(2 * Hd + g ) * Hd + h1];
        g_WP[idx * 3 + 0] = make_float4(ir0, iz0, in0, hr0);
        g_WP[idx * 3 + 1] = make_float4(hz0, hn0, ir1, iz1);
        g_WP[idx * 3 + 2] = make_float4(in1, hr1, hz1, hn1);
    }
    // fused GRU biases
    for (int g = t0; g < Hd; g += stride) {
        g_BI[g] = make_float4(b_ih[g] + b_hh[g],
                              b_ih[Hd + g] + b_hh[Hd + g],
                              b_ih[2 * Hd + g],
                              b_hh[2 * Hd + g]);
    }
}

__device__ __forceinline__ float sigmoidf_(float x) {
    return 1.f / (1.f + __expf(-x));
}
__device__ __forceinline__ float tanhf_(float x) {
    // tanh(x) = 1 - 2/(1+e^{2x}); exact limits at +-inf, ~1e-6 rel err
    return 1.f - 2.f / (1.f + __expf(2.f * x));
}

// Dynamic smem layout (floats):
//  hidA[100*RS] hidB[100*RS] msgb[100*RS] u0[100*RS] u1[100*RS] nod[40*RS]
//  gsum[128] rowsum[32] sv[32*16] | ints: scnt[32] maxs[8 pad] sj[32*16] stp[32*16]
// (u0/u1 doubles as the 32*EROW edge staging buffer during setup; 4224 <= 6600 floats)
#define SMEM_FLOATS (5*Hd*RS + Fdim*RS + 128 + 32 + 32*MAXNBR + 32 + 8 + 32*MAXNBR + 32*MAXNBR)

__global__ __launch_bounds__(TPB, 2)
void mpnn_kernel(const float* __restrict__ nodes,
                 const float* __restrict__ edges,
                 const float* __restrict__ Wg,
                 const float* __restrict__ bg,
                 const float* __restrict__ We,
                 const float* __restrict__ be,
                 const float* __restrict__ Wo,
                 const float* __restrict__ bo,
                 float* __restrict__ out)
{
    extern __shared__ float sm[];
    float*  hidA   = sm;
    float*  hidB   = hidA + Hd * RS;
    float*  msgb   = hidB + Hd * RS;
    float*  u0     = msgb + Hd * RS;
    float*  u1     = u0 + Hd * RS;
    float*  nod    = u1 + Hd * RS;              // 40*RS
    float*  gsum   = nod + Fdim * RS;           // 128
    float*  rowsum = gsum + 128;                // 32
    float*  sv     = rowsum + 32;               // 32*MAXNBR (slot edge values)
    int*    scnt   = (int*)(sv + 32 * MAXNBR);  // 32
    int*    maxs_s = scnt + 32;                 // 1 (+7 pad)
    int*    sj     = maxs_s + 8;                // 32*MAXNBR (slot neighbor)
    int*    stp    = sj + 32 * MAXNBR;          // 32*MAXNBR (slot type)
    float*  ebuf   = u0;                        // setup-phase overlay: 32*EROW floats

    const int tid  = threadIdx.x;
    const int lane = tid & 31;
    const int warp = tid >> 5;
    const int b    = blockIdx.x;
    const int NW   = TPB / 32;

    // ---- setup: nodes (transposed to [f][i]) ----
    for (int t = tid; t < Nn * Fdim; t += TPB) {
        int i = t / Fdim, f = t % Fdim;
        nod[f * RS + i] = nodes[(b * Nn + i) * Fdim + f];
    }
    // ---- cooperative stage of this graph's edge block into SMEM (full-MLP HBM pull) ----
    {
        const float4* esrc = reinterpret_cast<const float4*>(
            edges + (size_t)b * Nn * Nn * EFd);
        for (int t = tid; t < Nn * Nn; t += TPB) {
            int i = t >> 5, j = t & 31;
            *reinterpret_cast<float4*>(ebuf + i * EROW + j * 4) = esrc[i * Nn + j];
        }
    }
    __syncthreads();
    // ---- deterministic per-node slot list (one slot per nonzero edge-feature) ----
    if (tid < Nn) {
        int i = tid;
        int cnt = 0; float rs = 0.f;
        for (int j = 0; j < Nn; j++) {
            float4 e = *reinterpret_cast<const float4*>(ebuf + i * EROW + j * 4);
            float s = e.x + e.y + e.z + e.w;
            rs += s;
            if (s != 0.f) {   // matches nonzero(adjacency) semantics
                float ef[4] = {e.x, e.y, e.z, e.w};
                #pragma unroll
                for (int f = 0; f < 4; f++) {
                    if (ef[f] != 0.f && cnt < MAXNBR) {
                        sj [i * MAXNBR + cnt] = j;
                        stp[i * MAXNBR + cnt] = f;
                        sv [i * MAXNBR + cnt] = ef[f];
                        cnt++;
                    }
                }
            }
        }
        scnt[i]   = cnt;
        rowsum[i] = rs;
    }
    __syncthreads();
    if (tid == 0) {
        int m = 0;
        for (int i = 0; i < Nn; i++) m = max(m, scnt[i]);
        maxs_s[0] = m;
    }
    // ---- init hidden ----
    for (int t = tid; t < Hd * Nn; t += TPB) {
        int h = t >> 5, i = t & 31;
        hidA[h * RS + i] = (h < Fdim) ? nod[h * RS + i] : 0.f;
    }
    __syncthreads();

    const int maxs   = maxs_s[0];
    const int nPairs = max(1, (maxs + 1) >> 1);

    float* cur = hidA;
    float* nxt = hidB;

    for (int pass = 0; pass < PASSES; pass++) {
        // ================= messages =================
        for (int p = 0; p < nPairs; p++) {
            if (p > 0) __syncthreads();   // previous GEMM done reading u
            // build gathered columns u0,u1 for slot pair (2p, 2p+1)
            const int s0 = 2 * p, s1 = 2 * p + 1;
            for (int t = tid; t < Hd * Nn; t += TPB) {
                int h = t >> 5, i = t & 31;
                int   c  = scnt[i];
                float v0 = (s0 < c) ? sv[i * MAXNBR + s0] : 0.f;
                int   j0 = (s0 < c) ? sj[i * MAXNBR + s0] : 0;
                float v1 = (s1 < c) ? sv[i * MAXNBR + s1] : 0.f;
                int   j1 = (s1 < c) ? sj[i * MAXNBR + s1] : 0;
                u0[h * RS + i] = v0 * cur[h * RS + j0];
                u1[h * RS + i] = v1 * cur[h * RS + j1];
            }
            __syncthreads();
            // per-lane (node) edge types for this pair
            int   c   = scnt[lane];
            int   t0l = (s0 < c) ? stp[lane * MAXNBR + s0] : 0;
            int   t1l = (s1 < c) ? stp[lane * MAXNBR + s1] : 0;
            // msg[m][i] += W_{t0}[m,:] u0[:,i] + W_{t1}[m,:] u1[:,i]
            // type-interleaved layout: element (h*25+g)*4 + t; per-h stride = 100 float4
            for (int g = warp; g < 25; g += NW) {
                const float4* w0 = g_W2i + g * 4 + t0l;
                const float4* w1 = g_W2i + g * 4 + t1l;
                float4 acc;
                if (p == 0) {
                    acc = make_float4(0.f, 0.f, 0.f, 0.f);
                } else {
                    acc.x = msgb[(4 * g + 0) * RS + lane];
                    acc.y = msgb[(4 * g + 1) * RS + lane];
                    acc.z = msgb[(4 * g + 2) * RS + lane];
                    acc.w = msgb[(4 * g + 3) * RS + lane];
                }
                #pragma unroll 4
                for (int h = 0; h < Hd; h++) {
                    float  x0 = u0[h * RS + lane];
                    float  x1 = u1[h * RS + lane];
                    float4 a  = w0[h * 100];
                    float4 bb = w1[h * 100];
                    acc.x += a.x * x0 + bb.x * x1;
                    acc.y += a.y * x0 + bb.y * x1;
                    acc.z += a.z * x0 + bb.z * x1;
                    acc.w += a.w * x0 + bb.w * x1;
                }
                msgb[(4 * g + 0) * RS + lane] = acc.x;
                msgb[(4 * g + 1) * RS + lane] = acc.y;
                msgb[(4 * g + 2) * RS + lane] = acc.z;
                msgb[(4 * g + 3) * RS + lane] = acc.w;
            }
        }
        __syncthreads();
        // ================= fused GRU =================
        {
            float maskv = (rowsum[lane] != 0.f) ? 1.f : 0.f;
            for (int g = warp; g < Hd; g += NW) {
                float4 acc = make_float4(0.f, 0.f, 0.f, 0.f);  // {r_pre, z_pre, inn, hn}
                const float4* wp = g_WP + (size_t)g * 3;
                #pragma unroll 2
                for (int hh2 = 0; hh2 < Hd / 2; hh2++) {
                    int h0 = 2 * hh2, h1 = 2 * hh2 + 1;
                    float xm0 = msgb[h0 * RS + lane];
                    float xh0 = cur [h0 * RS + lane];
                    float xm1 = msgb[h1 * RS + lane];
                    float xh1 = cur [h1 * RS + lane];
                    float4 w0 = wp[0];
                    float4 w1 = wp[1];
                    float4 w2 = wp[2];
                    wp += Hd * 3;
                    acc.x += w0.x * xm0 + w0.w * xh0 + w1.z * xm1 + w2.y * xh1;
                    acc.y += w0.y * xm0 + w1.x * xh0 + w1.w * xm1 + w2.z * xh1;
                    acc.z += w0.z * xm0 + w2.x * xm1;
                    acc.w += w1.y * xh0 + w2.w * xh1;
                }
                float4 bi = g_BI[g];
                float r  = sigmoidf_(acc.x + bi.x);
                float z  = sigmoidf_(acc.y + bi.y);
                float n  = tanhf_(acc.z + bi.z + r * (acc.w + bi.w));
                float h0 = cur[g * RS + lane];
                float h1v = (1.f - z) * n + z * h0;
                nxt[g * RS + lane] = (maskv != 0.f) ? h1v : h0;
            }
        }
        __syncthreads();
        float* t2 = cur; cur = nxt; nxt = t2;
    }

    // ---- fused readout (cur = final hidden) ----
    // For each output group: gate_pre = Wg.[hid;nod] + bg ; emb = sigmoid(gate_pre)*(We.hid + be)
    // computed in ONE pass sharing the x loads; then masked node-reduction via shuffles.
    {
        float maskv = (rowsum[lane] != 0.f) ? 1.f : 0.f;
        for (int g = warp; g < 25; g += NW) {
            float4 ag = make_float4(0.f, 0.f, 0.f, 0.f);  // Wg accumulators
            float4 ae = make_float4(0.f, 0.f, 0.f, 0.f);  // We accumulators
            #pragma unroll 4
            for (int c = 0; c < Hd; c++) {
                float  x  = cur[c * RS + lane];
                float4 wg = *reinterpret_cast<const float4*>(Wg + c * Hd + 4 * g);
                float4 we = *reinterpret_cast<const float4*>(We + c * Hd + 4 * g);
                ag.x += wg.x * x; ag.y += wg.y * x; ag.z += wg.z * x; ag.w += wg.w * x;
                ae.x += we.x * x; ae.y += we.y * x; ae.z += we.z * x; ae.w += we.w * x;
            }
            #pragma unroll 4
            for (int c = 0; c < Fdim; c++) {
                float  x  = nod[c * RS + lane];
                float4 wg = *reinterpret_cast<const float4*>(Wg + (Hd + c) * Hd + 4 * g);
                ag.x += wg.x * x; ag.y += wg.y * x; ag.z += wg.z * x; ag.w += wg.w * x;
            }
            float e0 = maskv * sigmoidf_(ag.x + bg[4 * g + 0]) * (ae.x + be[4 * g + 0]);
            float e1 = maskv * sigmoidf_(ag.y + bg[4 * g + 1]) * (ae.y + be[4 * g + 1]);
            float e2 = maskv * sigmoidf_(ag.z + bg[4 * g + 2]) * (ae.z + be[4 * g + 2]);
            float e3 = maskv * sigmoidf_(ag.w + bg[4 * g + 3]) * (ae.w + be[4 * g + 3]);
            #pragma unroll
            for (int off = 16; off; off >>= 1) {
                e0 += __shfl_xor_sync(0xffffffffu, e0, off);
                e1 += __shfl_xor_sync(0xffffffffu, e1, off);
                e2 += __shfl_xor_sync(0xffffffffu, e2, off);
                e3 += __shfl_xor_sync(0xffffffffu, e3, off);
            }
            if (lane == 0) {
                gsum[4 * g + 0] = e0; gsum[4 * g + 1] = e1;
                gsum[4 * g + 2] = e2; gsum[4 * g + 3] = e3;
            }
        }
    }
    __syncthreads();
    // final projection: out[b][o] = gsum @ Wo + bo
    if (tid < OUTD) {
        float acc = bo[tid];
        #pragma unroll 4
        for (int h = 0; h < Hd; h++) acc += gsum[h] * Wo[h * OUTD + tid];
        out[b * OUTD + tid] = acc;
    }
}

extern "C" void kernel_launch(void* const* d_in, const int* in_sizes, int n_in,
                              void* d_out, int out_size) {
    const float* nodes = (const float*)d_in[0];
    const float* edges = (const float*)d_in[1];
    const float* W_msg = (const float*)d_in[2];
    const float* W_ih  = (const float*)d_in[3];
    const float* W_hh  = (const float*)d_in[4];
    const float* b_ih  = (const float*)d_in[5];
    const float* b_hh  = (const float*)d_in[6];
    const float* Wg    = (const float*)d_in[7];
    const float* bg    = (const float*)d_in[8];
    const float* We    = (const float*)d_in[9];
    const float* be    = (const float*)d_in[10];
    const float* Wo    = (const float*)d_in[11];
    const float* bo    = (const float*)d_in[12];
    float* out = (float*)d_out;

    prep_kernel<<<64, 256>>>(W_msg, W_ih, W_hh, b_ih, b_hh);

    size_t smem = (size_t)SMEM_FLOATS * sizeof(float);
    cudaFuncSetAttribute(mpnn_kernel, cudaFuncAttributeMaxDynamicSharedMemorySize, (int)smem);
    mpnn_kernel<<<Bb, TPB, smem>>>(nodes, edges,
                                   Wg, bg, We, be, Wo, bo, out);
}

// round 8
// speedup vs baseline: 1.1803x; 1.1803x over previous
#include <cuda_runtime.h>
#include <cstdint>
#include <math.h>

// Problem constants
#define Hd   100
#define Fdim 40
#define Nn   32
#define Bb   256
#define EFd  4
#define OUTD 128
#define PASSES 3
#define TPB  512
#define MAXNBR 16
#define RS   33      // padded row stride (odd -> conflict-free strided smem access)
#define EROW 132     // edge-stage row stride in floats

// ---- Pre-transposed weights (rebuilt by prep_kernel every launch; deterministic) ----
// Type-interleaved msg weights: g_W2i[((h*25 + g)*4) + t] = float4 { W_msg[m=4g..4g+3, h, f=t] }
__device__ __align__(128) float4 g_W2i[Hd * 25 * EFd];
// g_WP[(hh2*100 + g)*3 + k] : 12 packed GRU weights for gate-row g, reduction rows 2*hh2, 2*hh2+1
__device__ __align__(16) float4 g_WP[(Hd / 2) * Hd * 3];
// g_BI[g] = {b_ih_r+b_hh_r, b_ih_z+b_hh_z, b_ih_n, b_hh_n}
__device__ __align__(16) float4 g_BI[Hd];

__global__ void prep_kernel(const float* __restrict__ W_msg,
                            const float* __restrict__ W_ih,
                            const float* __restrict__ W_hh,
                            const float* __restrict__ b_ih,
                            const float* __restrict__ b_hh) {
    int t0 = blockIdx.x * blockDim.x + threadIdx.x;
    int stride = gridDim.x * blockDim.x;
    for (int idx = t0; idx < Hd * 25 * EFd; idx += stride) {
        int t  = idx & 3;
        int hg = idx >> 2;
        int g  = hg % 25;
        int h  = hg / 25;
        float4 v;
        v.x = W_msg[((4 * g + 0) * Hd + h) * EFd + t];
        v.y = W_msg[((4 * g + 1) * Hd + h) * EFd + t];
        v.z = W_msg[((4 * g + 2) * Hd + h) * EFd + t];
        v.w = W_msg[((4 * g + 3) * Hd + h) * EFd + t];
        g_W2i[idx] = v;
    }
    for (int idx = t0; idx < (Hd / 2) * Hd; idx += stride) {
        int g   = idx % Hd;
        int hh2 = idx / Hd;
        int h0 = 2 * hh2, h1 = 2 * hh2 + 1;
        float ir0 = W_ih[(g          ) * Hd + h0];
        float iz0 = W_ih[(Hd + g     ) * Hd + h0];
        float in0 = W_ih[(2 * Hd + g ) * Hd + h0];
        float hr0 = W_hh[(g          ) * Hd + h0];
        float hz0 = W_hh[(Hd + g     ) * Hd + h0];
        float hn0 = W_hh[(2 * Hd + g ) * Hd + h0];
        float ir1 = W_ih[(g          ) * Hd + h1];
        float iz1 = W_ih[(Hd + g     ) * Hd + h1];
        float in1 = W_ih[(2 * Hd + g ) * Hd + h1];
        float hr1 = W_hh[(g          ) * Hd + h1];
        float hz1 = W_hh[(Hd + g     ) * Hd + h1];
        float hn1 = W_hh[(2 * Hd + g ) * Hd + h1];
        g_WP[idx * 3 + 0] = make_float4(ir0, iz0, in0, hr0);
        g_WP[idx * 3 + 1] = make_float4(hz0, hn0, ir1, iz1);
        g_WP[idx * 3 + 2] = make_float4(in1, hr1, hz1, hn1);
    }
    for (int g = t0; g < Hd; g += stride) {
        g_BI[g] = make_float4(b_ih[g] + b_hh[g],
                              b_ih[Hd + g] + b_hh[Hd + g],
                              b_ih[2 * Hd + g],
                              b_hh[2 * Hd + g]);
    }
}

__device__ __forceinline__ float sigmoidf_(float x) {
    return 1.f / (1.f + __expf(-x));
}
__device__ __forceinline__ float tanhf_(float x) {
    return 1.f - 2.f / (1.f + __expf(2.f * x));
}

// Dynamic smem layout (floats):
//  hidA[100*RS] hidB[100*RS] msgb[100*RS] nod[40*RS]
//  gsum[128] rowsum[32] sv[32*16] | ints: scnt[32] maxs[8] sj[32*16] stp[32*16]
// (hidB+msgb doubles as the 32*EROW edge staging buffer during setup)
#define SMEM_FLOATS (3*Hd*RS + Fdim*RS + 128 + 32 + 32*MAXNBR + 32 + 8 + 32*MAXNBR + 32*MAXNBR)

__global__ __launch_bounds__(TPB, 2)
void mpnn_kernel(const float* __restrict__ nodes,
                 const float* __restrict__ edges,
                 const float* __restrict__ Wg,
                 const float* __restrict__ bg,
                 const float* __restrict__ We,
                 const float* __restrict__ be,
                 const float* __restrict__ Wo,
                 const float* __restrict__ bo,
                 float* __restrict__ out)
{
    extern __shared__ float sm[];
    float*  hidA   = sm;
    float*  hidB   = hidA + Hd * RS;
    float*  msgb   = hidB + Hd * RS;
    float*  nod    = msgb + Hd * RS;            // 40*RS
    float*  gsum   = nod + Fdim * RS;           // 128
    float*  rowsum = gsum + 128;                // 32
    float*  sv     = rowsum + 32;               // 32*MAXNBR
    int*    scnt   = (int*)(sv + 32 * MAXNBR);  // 32
    int*    maxs_s = scnt + 32;                 // 1 (+7 pad)
    int*    sj     = maxs_s + 8;                // 32*MAXNBR
    int*    stp    = sj + 32 * MAXNBR;          // 32*MAXNBR
    float*  ebuf   = hidB;                      // setup overlay: 32*EROW floats

    const int tid  = threadIdx.x;
    const int lane = tid & 31;
    const int warp = tid >> 5;
    const int b    = blockIdx.x;
    const int NW   = TPB / 32;   // 16

    // ---- setup: nodes (transposed to [f][i]) ----
    for (int t = tid; t < Nn * Fdim; t += TPB) {
        int i = t / Fdim, f = t % Fdim;
        nod[f * RS + i] = nodes[(b * Nn + i) * Fdim + f];
    }
    // ---- cooperative stage of this graph's edge block into SMEM ----
    {
        const float4* esrc = reinterpret_cast<const float4*>(
            edges + (size_t)b * Nn * Nn * EFd);
        for (int t = tid; t < Nn * Nn; t += TPB) {
            int i = t >> 5, j = t & 31;
            *reinterpret_cast<float4*>(ebuf + i * EROW + j * 4) = esrc[i * Nn + j];
        }
    }
    __syncthreads();
    // ---- deterministic per-node slot list ----
    if (tid < Nn) {
        int i = tid;
        int cnt = 0; float rs = 0.f;
        for (int j = 0; j < Nn; j++) {
            float4 e = *reinterpret_cast<const float4*>(ebuf + i * EROW + j * 4);
            float s = e.x + e.y + e.z + e.w;
            rs += s;
            if (s != 0.f) {
                float ef[4] = {e.x, e.y, e.z, e.w};
                #pragma unroll
                for (int f = 0; f < 4; f++) {
                    if (ef[f] != 0.f && cnt < MAXNBR) {
                        sj [i * MAXNBR + cnt] = j;
                        stp[i * MAXNBR + cnt] = f;
                        sv [i * MAXNBR + cnt] = ef[f];
                        cnt++;
                    }
                }
            }
        }
        scnt[i]   = cnt;
        rowsum[i] = rs;
    }
    __syncthreads();
    if (tid == 0) {
        int m = 0;
        for (int i = 0; i < Nn; i++) m = max(m, scnt[i]);
        maxs_s[0] = m;
    }
    // ---- init hidden ----
    for (int t = tid; t < Hd * Nn; t += TPB) {
        int h = t >> 5, i = t & 31;
        hidA[h * RS + i] = (h < Fdim) ? nod[h * RS + i] : 0.f;
    }
    __syncthreads();

    const int maxs   = maxs_s[0];
    const int nPairs = max(1, (maxs + 1) >> 1);
    const int myc    = scnt[lane];
    const float maskv = (rowsum[lane] != 0.f) ? 1.f : 0.f;

    float* cur = hidA;
    float* nxt = hidB;

    for (int pass = 0; pass < PASSES; pass++) {
        // ===== messages: warp handles groups gA=warp (+ gB=warp+16 if <25) =====
        // Direct per-lane gather from cur; accumulate in registers; no internal barriers.
        {
            const int gA = warp;
            const int gB = warp + NW;
            float4 accA = make_float4(0.f, 0.f, 0.f, 0.f);
            float4 accB = make_float4(0.f, 0.f, 0.f, 0.f);
            for (int p = 0; p < nPairs; p++) {
                const int s0 = 2 * p, s1 = 2 * p + 1;
                float v0 = (s0 < myc) ? sv[lane * MAXNBR + s0] : 0.f;
                int   j0 = (s0 < myc) ? sj[lane * MAXNBR + s0] : 0;
                int   t0 = (s0 < myc) ? stp[lane * MAXNBR + s0] : 0;
                float v1 = (s1 < myc) ? sv[lane * MAXNBR + s1] : 0.f;
                int   j1 = (s1 < myc) ? sj[lane * MAXNBR + s1] : 0;
                int   t1 = (s1 < myc) ? stp[lane * MAXNBR + s1] : 0;
                if (gB < 25) {
                    const float4* wA0 = g_W2i + gA * 4 + t0;
                    const float4* wA1 = g_W2i + gA * 4 + t1;
                    const float4* wB0 = g_W2i + gB * 4 + t0;
                    const float4* wB1 = g_W2i + gB * 4 + t1;
                    #pragma unroll 4
                    for (int h = 0; h < Hd; h++) {
                        float x0 = v0 * cur[h * RS + j0];
                        float x1 = v1 * cur[h * RS + j1];
                        float4 a0 = wA0[h * 100];
                        float4 a1 = wA1[h * 100];
                        float4 b0 = wB0[h * 100];
                        float4 b1 = wB1[h * 100];
                        accA.x += a0.x * x0 + a1.x * x1;
                        accA.y += a0.y * x0 + a1.y * x1;
                        accA.z += a0.z * x0 + a1.z * x1;
                        accA.w += a0.w * x0 + a1.w * x1;
                        accB.x += b0.x * x0 + b1.x * x1;
                        accB.y += b0.y * x0 + b1.y * x1;
                        accB.z += b0.z * x0 + b1.z * x1;
                        accB.w += b0.w * x0 + b1.w * x1;
                    }
                } else {
                    const float4* wA0 = g_W2i + gA * 4 + t0;
                    const float4* wA1 = g_W2i + gA * 4 + t1;
                    #pragma unroll 4
                    for (int h = 0; h < Hd; h++) {
                        float x0 = v0 * cur[h * RS + j0];
                        float x1 = v1 * cur[h * RS + j1];
                        float4 a0 = wA0[h * 100];
                        float4 a1 = wA1[h * 100];
                        accA.x += a0.x * x0 + a1.x * x1;
                        accA.y += a0.y * x0 + a1.y * x1;
                        accA.z += a0.z * x0 + a1.z * x1;
                        accA.w += a0.w * x0 + a1.w * x1;
                    }
                }
            }
            msgb[(4 * gA + 0) * RS + lane] = accA.x;
            msgb[(4 * gA + 1) * RS + lane] = accA.y;
            msgb[(4 * gA + 2) * RS + lane] = accA.z;
            msgb[(4 * gA + 3) * RS + lane] = accA.w;
            if (gB < 25) {
                msgb[(4 * gB + 0) * RS + lane] = accB.x;
                msgb[(4 * gB + 1) * RS + lane] = accB.y;
                msgb[(4 * gB + 2) * RS + lane] = accB.z;
                msgb[(4 * gB + 3) * RS + lane] = accB.w;
            }
        }
        __syncthreads();
        // ===== fused GRU: warp handles gate-row pair (2gp, 2gp+1) per x-load =====
        for (int gp = warp; gp < Hd / 2; gp += NW) {
            const int g0 = 2 * gp, g1 = 2 * gp + 1;
            float4 ac0 = make_float4(0.f, 0.f, 0.f, 0.f);
            float4 ac1 = make_float4(0.f, 0.f, 0.f, 0.f);
            const float4* wp = g_WP + 3 * g0;
            #pragma unroll 2
            for (int hh2 = 0; hh2 < Hd / 2; hh2++) {
                int h0 = 2 * hh2, h1 = 2 * hh2 + 1;
                float xm0 = msgb[h0 * RS + lane];
                float xh0 = cur [h0 * RS + lane];
                float xm1 = msgb[h1 * RS + lane];
                float xh1 = cur [h1 * RS + lane];
                float4 w0 = wp[0];
                float4 w1 = wp[1];
                float4 w2 = wp[2];
                float4 w3 = wp[3];
                float4 w4 = wp[4];
                float4 w5 = wp[5];
                wp += Hd * 3;
                ac0.x += w0.x * xm0 + w0.w * xh0 + w1.z * xm1 + w2.y * xh1;
                ac0.y += w0.y * xm0 + w1.x * xh0 + w1.w * xm1 + w2.z * xh1;
                ac0.z += w0.z * xm0 + w2.x * xm1;
                ac0.w += w1.y * xh0 + w2.w * xh1;
                ac1.x += w3.x * xm0 + w3.w * xh0 + w4.z * xm1 + w5.y * xh1;
                ac1.y += w3.y * xm0 + w4.x * xh0 + w4.w * xm1 + w5.z * xh1;
                ac1.z += w3.z * xm0 + w5.x * xm1;
                ac1.w += w4.y * xh0 + w5.w * xh1;
            }
            float4 bi0 = g_BI[g0];
            float4 bi1 = g_BI[g1];
            float r0 = sigmoidf_(ac0.x + bi0.x);
            float z0 = sigmoidf_(ac0.y + bi0.y);
            float n0 = tanhf_(ac0.z + bi0.z + r0 * (ac0.w + bi0.w));
            float o0 = cur[g0 * RS + lane];
            float r1 = sigmoidf_(ac1.x + bi1.x);
            float z1 = sigmoidf_(ac1.y + bi1.y);
            float n1 = tanhf_(ac1.z + bi1.z + r1 * (ac1.w + bi1.w));
            float o1 = cur[g1 * RS + lane];
            float u0v = (1.f - z0) * n0 + z0 * o0;
            float u1v = (1.f - z1) * n1 + z1 * o1;
            nxt[g0 * RS + lane] = (maskv != 0.f) ? u0v : o0;
            nxt[g1 * RS + lane] = (maskv != 0.f) ? u1v : o1;
        }
        __syncthreads();
        float* t2 = cur; cur = nxt; nxt = t2;
    }

    // ---- fused readout (cur = final hidden) ----
    for (int g = warp; g < 25; g += NW) {
        float4 ag = make_float4(0.f, 0.f, 0.f, 0.f);
        float4 ae = make_float4(0.f, 0.f, 0.f, 0.f);
        #pragma unroll 4
        for (int c = 0; c < Hd; c++) {
            float  x  = cur[c * RS + lane];
            float4 wg = *reinterpret_cast<const float4*>(Wg + c * Hd + 4 * g);
            float4 we = *reinterpret_cast<const float4*>(We + c * Hd + 4 * g);
            ag.x += wg.x * x; ag.y += wg.y * x; ag.z += wg.z * x; ag.w += wg.w * x;
            ae.x += we.x * x; ae.y += we.y * x; ae.z += we.z * x; ae.w += we.w * x;
        }
        #pragma unroll 4
        for (int c = 0; c < Fdim; c++) {
            float  x  = nod[c * RS + lane];
            float4 wg = *reinterpret_cast<const float4*>(Wg + (Hd + c) * Hd + 4 * g);
            ag.x += wg.x * x; ag.y += wg.y * x; ag.z += wg.z * x; ag.w += wg.w * x;
        }
        float e0 = maskv * sigmoidf_(ag.x + bg[4 * g + 0]) * (ae.x + be[4 * g + 0]);
        float e1 = maskv * sigmoidf_(ag.y + bg[4 * g + 1]) * (ae.y + be[4 * g + 1]);
        float e2 = maskv * sigmoidf_(ag.z + bg[4 * g + 2]) * (ae.z + be[4 * g + 2]);
        float e3 = maskv * sigmoidf_(ag.w + bg[4 * g + 3]) * (ae.w + be[4 * g + 3]);
        #pragma unroll
        for (int off = 16; off; off >>= 1) {
            e0 += __shfl_xor_sync(0xffffffffu, e0, off);
            e1 += __shfl_xor_sync(0xffffffffu, e1, off);
            e2 += __shfl_xor_sync(0xffffffffu, e2, off);
            e3 += __shfl_xor_sync(0xffffffffu, e3, off);
        }
        if (lane == 0) {
            gsum[4 * g + 0] = e0; gsum[4 * g + 1] = e1;
            gsum[4 * g + 2] = e2; gsum[4 * g + 3] = e3;
        }
    }
    __syncthreads();
    // final projection: out[b][o] = gsum @ Wo + bo
    if (tid < OUTD) {
        float acc = bo[tid];
        #pragma unroll 4
        for (int h = 0; h < Hd; h++) acc += gsum[h] * Wo[h * OUTD + tid];
        out[b * OUTD + tid] = acc;
    }
}

extern "C" void kernel_launch(void* const* d_in, const int* in_sizes, int n_in,
                              void* d_out, int out_size) {
    const float* nodes = (const float*)d_in[0];
    const float* edges = (const float*)d_in[1];
    const float* W_msg = (const float*)d_in[2];
    const float* W_ih  = (const float*)d_in[3];
    const float* W_hh  = (const float*)d_in[4];
    const float* b_ih  = (const float*)d_in[5];
    const float* b_hh  = (const float*)d_in[6];
    const float* Wg    = (const float*)d_in[7];
    const float* bg    = (const float*)d_in[8];
    const float* We    = (const float*)d_in[9];
    const float* be    = (const float*)d_in[10];
    const float* Wo    = (const float*)d_in[11];
    const float* bo    = (const float*)d_in[12];
    float* out = (float*)d_out;

    prep_kernel<<<64, 256>>>(W_msg, W_ih, W_hh, b_ih, b_hh);

    size_t smem = (size_t)SMEM_FLOATS * sizeof(float);
    cudaFuncSetAttribute(mpnn_kernel, cudaFuncAttributeMaxDynamicSharedMemorySize, (int)smem);
    mpnn_kernel<<<Bb, TPB, smem>>>(nodes, edges,
                                   Wg, bg, We, be, Wo, bo, out);
}